// round 1
// baseline (speedup 1.0000x reference)
#include <cuda_runtime.h>

#define NUM_E 8
#define TOK   16384
#define DIN   2048
#define DOUT  2048
#define RNK   64
#define LSCALE 2.0f

// Scratch for scaled LoRA mid activations: SCALE * (x @ w_a), [TOK, RNK] fp32.
__device__ float g_mid[TOK * RNK];

// Round fp32 -> tf32 (round-to-nearest). HW mma truncates, so pre-round to
// kill the ~2^-10 coherent truncation bias over K=2048.
__device__ __forceinline__ unsigned f2tf(float f) {
    unsigned u;
    asm("cvt.rna.tf32.f32 %0, %1;" : "=r"(u) : "f"(f));
    return u;
}

__device__ __forceinline__ void mma8(float* c,
                                     unsigned a0, unsigned a1, unsigned a2, unsigned a3,
                                     unsigned b0, unsigned b1) {
    asm volatile(
        "mma.sync.aligned.m16n8k8.row.col.f32.tf32.tf32.f32 "
        "{%0,%1,%2,%3}, {%4,%5,%6,%7}, {%8,%9}, {%0,%1,%2,%3};"
        : "+f"(c[0]), "+f"(c[1]), "+f"(c[2]), "+f"(c[3])
        : "r"(a0), "r"(a1), "r"(a2), "r"(a3), "r"(b0), "r"(b1));
}

__device__ __forceinline__ int find_expert(const int* __restrict__ tpe, int m0) {
    int e = 0, cum = 0;
#pragma unroll
    for (int i = 0; i < NUM_E; ++i) {
        cum += tpe[i];
        if (m0 >= cum) e++;
    }
    return e;
}

// ============================================================================
// Kernel 1: g_mid[T, 64] = LSCALE * (x @ w_a[e])   (per-expert, tf32 mma)
// Tiles: BM=128, BN=64, BK=32. 256 threads, warp grid 4(m) x 2(n),
// warp tile 32x32 -> mma tiles 2(m) x 4(n).
// ============================================================================
__global__ void __launch_bounds__(256)
lora_mid_kernel(const float* __restrict__ x, const int* __restrict__ tpe,
                const float* __restrict__ w_a)
{
    const int BM = 128, BK = 32;
    const int AST = 36;   // 32+4: frag LDS bank = (4g+t)%32, conflict-free
    const int BST = 72;   // 64+8: frag LDS bank = (8t+g)%32, conflict-free
    extern __shared__ __align__(16) unsigned smem[];
    unsigned* As = smem;                  // [2][BM*AST]
    unsigned* Bs = smem + 2 * BM * AST;   // [2][BK*BST]

    const int tid = threadIdx.x;
    const int m0 = blockIdx.y * BM;
    const int e = find_expert(tpe, m0);
    const float* wa = w_a + (size_t)e * DIN * RNK;

    const int warp = tid >> 5, lane = tid & 31;
    const int wm = warp >> 1, wn = warp & 1;
    const int g = lane >> 2, t = lane & 3;

    float acc[2][4][4];
#pragma unroll
    for (int i = 0; i < 2; i++)
#pragma unroll
        for (int j = 0; j < 4; j++)
#pragma unroll
            for (int k = 0; k < 4; k++) acc[i][j][k] = 0.f;

    float4 ra[4], rb[2];

    auto ldg = [&](int kt) {
        const int k0 = kt * BK;
#pragma unroll
        for (int i = 0; i < 4; ++i) {
            int idx = tid + i * 256;
            int row = idx >> 3, c4 = (idx & 7) * 4;
            ra[i] = *(const float4*)&x[(size_t)(m0 + row) * DIN + k0 + c4];
        }
#pragma unroll
        for (int i = 0; i < 2; ++i) {
            int idx = tid + i * 256;
            int row = idx >> 4, c4 = (idx & 15) * 4;
            rb[i] = *(const float4*)&wa[(size_t)(k0 + row) * RNK + c4];
        }
    };
    auto sts = [&](int buf) {
        unsigned* Ab = As + buf * BM * AST;
        unsigned* Bb = Bs + buf * BK * BST;
#pragma unroll
        for (int i = 0; i < 4; ++i) {
            int idx = tid + i * 256;
            int row = idx >> 3, c4 = (idx & 7) * 4;
            uint4 s = make_uint4(f2tf(ra[i].x), f2tf(ra[i].y), f2tf(ra[i].z), f2tf(ra[i].w));
            *(uint4*)&Ab[row * AST + c4] = s;
        }
#pragma unroll
        for (int i = 0; i < 2; ++i) {
            int idx = tid + i * 256;
            int row = idx >> 4, c4 = (idx & 15) * 4;
            uint4 s = make_uint4(f2tf(rb[i].x), f2tf(rb[i].y), f2tf(rb[i].z), f2tf(rb[i].w));
            *(uint4*)&Bb[row * BST + c4] = s;
        }
    };

    const int NKT = DIN / BK;  // 64
    ldg(0); sts(0); __syncthreads();

    for (int kt = 0; kt < NKT; ++kt) {
        const int buf = kt & 1;
        if (kt + 1 < NKT) ldg(kt + 1);
        unsigned* Ab = As + buf * BM * AST;
        unsigned* Bb = Bs + buf * BK * BST;
#pragma unroll
        for (int ks = 0; ks < 4; ++ks) {
            const int kk = ks * 8;
            unsigned af[2][4], bf[4][2];
#pragma unroll
            for (int mt = 0; mt < 2; ++mt) {
                int r = wm * 32 + mt * 16;
                af[mt][0] = Ab[(r + g) * AST + kk + t];
                af[mt][1] = Ab[(r + g + 8) * AST + kk + t];
                af[mt][2] = Ab[(r + g) * AST + kk + t + 4];
                af[mt][3] = Ab[(r + g + 8) * AST + kk + t + 4];
            }
#pragma unroll
            for (int nt = 0; nt < 4; ++nt) {
                int c = wn * 32 + nt * 8 + g;
                bf[nt][0] = Bb[(kk + t) * BST + c];
                bf[nt][1] = Bb[(kk + t + 4) * BST + c];
            }
#pragma unroll
            for (int mt = 0; mt < 2; ++mt)
#pragma unroll
                for (int nt = 0; nt < 4; ++nt)
                    mma8(acc[mt][nt], af[mt][0], af[mt][1], af[mt][2], af[mt][3],
                         bf[nt][0], bf[nt][1]);
        }
        if (kt + 1 < NKT) sts((kt + 1) & 1);
        __syncthreads();
    }

#pragma unroll
    for (int mt = 0; mt < 2; ++mt)
#pragma unroll
        for (int nt = 0; nt < 4; ++nt) {
            int r = m0 + wm * 32 + mt * 16 + g;
            int c = wn * 32 + nt * 8 + 2 * t;
            float2 v0 = {LSCALE * acc[mt][nt][0], LSCALE * acc[mt][nt][1]};
            float2 v1 = {LSCALE * acc[mt][nt][2], LSCALE * acc[mt][nt][3]};
            *(float2*)&g_mid[(size_t)r * RNK + c] = v0;
            *(float2*)&g_mid[(size_t)(r + 8) * RNK + c] = v1;
        }
}

// ============================================================================
// Kernel 2: out = x @ w_base[e] + g_mid @ w_b[e]
// Implemented as a single composite-K GEMM: K = DIN + RNK = 2112.
// For k-tiles < DIN: A <- x, B <- w_base; else: A <- g_mid, B <- w_b.
// Tiles: BM=128, BN=128, BK=32. 256 threads, warp grid 2(m) x 4(n),
// warp tile 64x32 -> mma tiles 4(m) x 4(n).
// ============================================================================
__global__ void __launch_bounds__(256)
main_gemm_kernel(const float* __restrict__ x, const int* __restrict__ tpe,
                 const float* __restrict__ w_base, const float* __restrict__ w_b,
                 float* __restrict__ out)
{
    const int BM = 128, BN = 128, BK = 32;
    const int AST = 36;    // 32+4
    const int BST = 136;   // 128+8
    extern __shared__ __align__(16) unsigned smem[];
    unsigned* As = smem;                  // [2][BM*AST]
    unsigned* Bs = smem + 2 * BM * AST;   // [2][BK*BST]

    const int tid = threadIdx.x;
    const int m0 = blockIdx.y * BM;
    const int n0 = blockIdx.x * BN;
    const int e = find_expert(tpe, m0);
    const float* wbase = w_base + (size_t)e * DIN * DOUT;
    const float* wlora = w_b + (size_t)e * RNK * DOUT;

    const int warp = tid >> 5, lane = tid & 31;
    const int wm = warp >> 2, wn = warp & 3;
    const int g = lane >> 2, t = lane & 3;

    float acc[4][4][4];
#pragma unroll
    for (int i = 0; i < 4; i++)
#pragma unroll
        for (int j = 0; j < 4; j++)
#pragma unroll
            for (int k = 0; k < 4; k++) acc[i][j][k] = 0.f;

    float4 ra[4], rb[4];

    auto ldg = [&](int kt) {
        const int k0 = kt * BK;
        const bool lora = (k0 >= DIN);
#pragma unroll
        for (int i = 0; i < 4; ++i) {
            int idx = tid + i * 256;
            int row = idx >> 3, c4 = (idx & 7) * 4;
            ra[i] = lora
                ? *(const float4*)&g_mid[(size_t)(m0 + row) * RNK + (k0 - DIN) + c4]
                : *(const float4*)&x[(size_t)(m0 + row) * DIN + k0 + c4];
        }
#pragma unroll
        for (int i = 0; i < 4; ++i) {
            int idx = tid + i * 256;
            int row = idx >> 5, c4 = (idx & 31) * 4;
            rb[i] = lora
                ? *(const float4*)&wlora[(size_t)(k0 - DIN + row) * DOUT + n0 + c4]
                : *(const float4*)&wbase[(size_t)(k0 + row) * DOUT + n0 + c4];
        }
    };
    auto sts = [&](int buf) {
        unsigned* Ab = As + buf * BM * AST;
        unsigned* Bb = Bs + buf * BK * BST;
#pragma unroll
        for (int i = 0; i < 4; ++i) {
            int idx = tid + i * 256;
            int row = idx >> 3, c4 = (idx & 7) * 4;
            uint4 s = make_uint4(f2tf(ra[i].x), f2tf(ra[i].y), f2tf(ra[i].z), f2tf(ra[i].w));
            *(uint4*)&Ab[row * AST + c4] = s;
        }
#pragma unroll
        for (int i = 0; i < 4; ++i) {
            int idx = tid + i * 256;
            int row = idx >> 5, c4 = (idx & 31) * 4;
            uint4 s = make_uint4(f2tf(rb[i].x), f2tf(rb[i].y), f2tf(rb[i].z), f2tf(rb[i].w));
            *(uint4*)&Bb[row * BST + c4] = s;
        }
    };

    const int NKT = (DIN + RNK) / BK;  // 66
    ldg(0); sts(0); __syncthreads();

    for (int kt = 0; kt < NKT; ++kt) {
        const int buf = kt & 1;
        if (kt + 1 < NKT) ldg(kt + 1);
        unsigned* Ab = As + buf * BM * AST;
        unsigned* Bb = Bs + buf * BK * BST;
#pragma unroll
        for (int ks = 0; ks < 4; ++ks) {
            const int kk = ks * 8;
            unsigned af[4][4], bf[4][2];
#pragma unroll
            for (int mt = 0; mt < 4; ++mt) {
                int r = wm * 64 + mt * 16;
                af[mt][0] = Ab[(r + g) * AST + kk + t];
                af[mt][1] = Ab[(r + g + 8) * AST + kk + t];
                af[mt][2] = Ab[(r + g) * AST + kk + t + 4];
                af[mt][3] = Ab[(r + g + 8) * AST + kk + t + 4];
            }
#pragma unroll
            for (int nt = 0; nt < 4; ++nt) {
                int c = wn * 32 + nt * 8 + g;
                bf[nt][0] = Bb[(kk + t) * BST + c];
                bf[nt][1] = Bb[(kk + t + 4) * BST + c];
            }
#pragma unroll
            for (int mt = 0; mt < 4; ++mt)
#pragma unroll
                for (int nt = 0; nt < 4; ++nt)
                    mma8(acc[mt][nt], af[mt][0], af[mt][1], af[mt][2], af[mt][3],
                         bf[nt][0], bf[nt][1]);
        }
        if (kt + 1 < NKT) sts((kt + 1) & 1);
        __syncthreads();
    }

#pragma unroll
    for (int mt = 0; mt < 4; ++mt)
#pragma unroll
        for (int nt = 0; nt < 4; ++nt) {
            int r = m0 + wm * 64 + mt * 16 + g;
            int c = n0 + wn * 32 + nt * 8 + 2 * t;
            float2 v0 = {acc[mt][nt][0], acc[mt][nt][1]};
            float2 v1 = {acc[mt][nt][2], acc[mt][nt][3]};
            *(float2*)&out[(size_t)r * DOUT + c] = v0;
            *(float2*)&out[(size_t)(r + 8) * DOUT + c] = v1;
        }
}

// ============================================================================
extern "C" void kernel_launch(void* const* d_in, const int* in_sizes, int n_in,
                              void* d_out, int out_size) {
    const float* x      = (const float*)d_in[0];
    const int*   tpe    = (const int*)d_in[1];
    const float* w_base = (const float*)d_in[2];
    const float* w_a    = (const float*)d_in[3];
    const float* w_b    = (const float*)d_in[4];
    float* out = (float*)d_out;
    (void)in_sizes; (void)n_in; (void)out_size;

    const int smem1 = 2 * (128 * 36 + 32 * 72) * 4;   // 55296 B
    const int smem2 = 2 * (128 * 36 + 32 * 136) * 4;  // 71680 B
    cudaFuncSetAttribute(lora_mid_kernel, cudaFuncAttributeMaxDynamicSharedMemorySize, smem1);
    cudaFuncSetAttribute(main_gemm_kernel, cudaFuncAttributeMaxDynamicSharedMemorySize, smem2);

    lora_mid_kernel<<<dim3(1, TOK / 128), 256, smem1>>>(x, tpe, w_a);
    main_gemm_kernel<<<dim3(DOUT / 128, TOK / 128), 256, smem2>>>(x, tpe, w_base, w_b, out);
}

// round 3
// speedup vs baseline: 1.3406x; 1.3406x over previous
#include <cuda_runtime.h>
#include <cstdint>

#define NUM_E 8
#define TOK   16384
#define DIN   2048
#define DOUT  2048
#define RNK   64
#define LSCALE 2.0f

// ---------------------------------------------------------------------------
// Scratch (allocation-free device globals)
// ---------------------------------------------------------------------------
__device__ float g_mid[TOK * RNK];          // tf32-rounded SCALE*(x@w_a)
__device__ float xR_g[(size_t)TOK * DIN];   // tf32-rounded x

// fp32 -> tf32 round-to-nearest
__device__ __forceinline__ unsigned f2tf(float f) {
    unsigned u;
    asm("cvt.rna.tf32.f32 %0, %1;" : "=r"(u) : "f"(f));
    return u;
}

__device__ __forceinline__ int find_expert(const int* __restrict__ tpe, int m0) {
    int e = 0, cum = 0;
#pragma unroll
    for (int i = 0; i < NUM_E; ++i) {
        cum += tpe[i];
        if (m0 >= cum) e++;
    }
    return e;
}

__device__ __forceinline__ uint32_t smem_u32(const void* p) {
    uint32_t a;
    asm("{ .reg .u64 t; cvta.to.shared.u64 t, %1; cvt.u32.u64 %0, t; }"
        : "=r"(a) : "l"(p));
    return a;
}

__device__ __forceinline__ void cp16(uint32_t dst, const void* src) {
    asm volatile("cp.async.cg.shared.global [%0], [%1], 16;" :: "r"(dst), "l"(src));
}
#define CP_COMMIT() asm volatile("cp.async.commit_group;" ::: "memory")
#define CP_WAIT(n)  asm volatile("cp.async.wait_group %0;" :: "n"(n) : "memory")

__device__ __forceinline__ void mma8(float* c,
                                     unsigned a0, unsigned a1, unsigned a2, unsigned a3,
                                     unsigned b0, unsigned b1) {
    asm volatile(
        "mma.sync.aligned.m16n8k8.row.col.f32.tf32.tf32.f32 "
        "{%0,%1,%2,%3}, {%4,%5,%6,%7}, {%8,%9}, {%0,%1,%2,%3};"
        : "+f"(c[0]), "+f"(c[1]), "+f"(c[2]), "+f"(c[3])
        : "r"(a0), "r"(a1), "r"(a2), "r"(a3), "r"(b0), "r"(b1));
}

// ---------------------------------------------------------------------------
// Kernel 0: xR = rna_tf32(x)
// ---------------------------------------------------------------------------
__global__ void __launch_bounds__(256)
round_x_kernel(const float* __restrict__ x) {
    size_t i = ((size_t)blockIdx.x * 256 + threadIdx.x) * 4;
    float4 v = *(const float4*)(x + i);
    uint4 u = make_uint4(f2tf(v.x), f2tf(v.y), f2tf(v.z), f2tf(v.w));
    *(uint4*)(xR_g + i) = u;
}

// ---------------------------------------------------------------------------
// Kernel 1: g_mid = rna_tf32(LSCALE * (x @ w_a[e]))
// ---------------------------------------------------------------------------
__global__ void __launch_bounds__(256)
lora_mid_kernel(const float* __restrict__ x, const int* __restrict__ tpe,
                const float* __restrict__ w_a)
{
    const int BMm = 128, BKm = 32;
    const int AST1 = 36;
    const int BST1 = 72;
    extern __shared__ __align__(16) unsigned smem1[];
    unsigned* As = smem1;
    unsigned* Bs = smem1 + 2 * BMm * AST1;

    const int tid = threadIdx.x;
    const int m0 = blockIdx.y * BMm;
    const int e = find_expert(tpe, m0);
    const float* wa = w_a + (size_t)e * DIN * RNK;

    const int warp = tid >> 5, lane = tid & 31;
    const int wm = warp >> 1, wn = warp & 1;
    const int g = lane >> 2, t = lane & 3;

    float acc[2][4][4];
#pragma unroll
    for (int i = 0; i < 2; i++)
#pragma unroll
        for (int j = 0; j < 4; j++)
#pragma unroll
            for (int k = 0; k < 4; k++) acc[i][j][k] = 0.f;

    float4 ra[4], rb[2];
    auto ldg = [&](int kt) {
        const int k0 = kt * BKm;
#pragma unroll
        for (int i = 0; i < 4; ++i) {
            int idx = tid + i * 256;
            int row = idx >> 3, c4 = (idx & 7) * 4;
            ra[i] = *(const float4*)&x[(size_t)(m0 + row) * DIN + k0 + c4];
        }
#pragma unroll
        for (int i = 0; i < 2; ++i) {
            int idx = tid + i * 256;
            int row = idx >> 4, c4 = (idx & 15) * 4;
            rb[i] = *(const float4*)&wa[(size_t)(k0 + row) * RNK + c4];
        }
    };
    auto sts = [&](int buf) {
        unsigned* Ab = As + buf * BMm * AST1;
        unsigned* Bb = Bs + buf * BKm * BST1;
#pragma unroll
        for (int i = 0; i < 4; ++i) {
            int idx = tid + i * 256;
            int row = idx >> 3, c4 = (idx & 7) * 4;
            uint4 s = make_uint4(f2tf(ra[i].x), f2tf(ra[i].y), f2tf(ra[i].z), f2tf(ra[i].w));
            *(uint4*)&Ab[row * AST1 + c4] = s;
        }
#pragma unroll
        for (int i = 0; i < 2; ++i) {
            int idx = tid + i * 256;
            int row = idx >> 4, c4 = (idx & 15) * 4;
            uint4 s = make_uint4(f2tf(rb[i].x), f2tf(rb[i].y), f2tf(rb[i].z), f2tf(rb[i].w));
            *(uint4*)&Bb[row * BST1 + c4] = s;
        }
    };

    const int NKTm = DIN / BKm;
    ldg(0); sts(0); __syncthreads();

    for (int kt = 0; kt < NKTm; ++kt) {
        const int buf = kt & 1;
        if (kt + 1 < NKTm) ldg(kt + 1);
        unsigned* Ab = As + buf * BMm * AST1;
        unsigned* Bb = Bs + buf * BKm * BST1;
#pragma unroll
        for (int ks = 0; ks < 4; ++ks) {
            const int kk = ks * 8;
            unsigned af[2][4], bf[4][2];
#pragma unroll
            for (int mt = 0; mt < 2; ++mt) {
                int r = wm * 32 + mt * 16;
                af[mt][0] = Ab[(r + g) * AST1 + kk + t];
                af[mt][1] = Ab[(r + g + 8) * AST1 + kk + t];
                af[mt][2] = Ab[(r + g) * AST1 + kk + t + 4];
                af[mt][3] = Ab[(r + g + 8) * AST1 + kk + t + 4];
            }
#pragma unroll
            for (int nt = 0; nt < 4; ++nt) {
                int c = wn * 32 + nt * 8 + g;
                bf[nt][0] = Bb[(kk + t) * BST1 + c];
                bf[nt][1] = Bb[(kk + t + 4) * BST1 + c];
            }
#pragma unroll
            for (int mt = 0; mt < 2; ++mt)
#pragma unroll
                for (int nt = 0; nt < 4; ++nt)
                    mma8(acc[mt][nt], af[mt][0], af[mt][1], af[mt][2], af[mt][3],
                         bf[nt][0], bf[nt][1]);
        }
        if (kt + 1 < NKTm) sts((kt + 1) & 1);
        __syncthreads();
    }

#pragma unroll
    for (int mt = 0; mt < 2; ++mt)
#pragma unroll
        for (int nt = 0; nt < 4; ++nt) {
            int r = m0 + wm * 32 + mt * 16 + g;
            int c = wn * 32 + nt * 8 + 2 * t;
            uint2 v0 = {f2tf(LSCALE * acc[mt][nt][0]), f2tf(LSCALE * acc[mt][nt][1])};
            uint2 v1 = {f2tf(LSCALE * acc[mt][nt][2]), f2tf(LSCALE * acc[mt][nt][3])};
            *(uint2*)&g_mid[(size_t)r * RNK + c] = v0;
            *(uint2*)&g_mid[(size_t)(r + 8) * RNK + c] = v1;
        }
}

// ---------------------------------------------------------------------------
// Kernel 2: main GEMM. out = xR @ w_base[e] + g_mid @ w_b[e]  (composite K)
// BM=128 BN=128 BK=32, 3-stage cp.async pipeline, 8 warps, 2 CTAs/SM.
// Warp grid 2(m) x 4(n), warp tile 64x32, mma tiles 4(m) x 4(n).
// ---------------------------------------------------------------------------
#define BM   128
#define BN   128
#define BK   32
#define STG  3
#define AST  36
#define BST  136
#define A_FL (BM * AST)              // 4608 floats
#define B_FL (BK * BST)              // 4352 floats
#define STAGE_FL (A_FL + B_FL)       // 8960 floats
#define NKT  ((DIN + RNK) / BK)      // 66
#define GEMM_SMEM (STG * STAGE_FL * 4)   // 107520 B

__global__ void __launch_bounds__(256, 2)
gemm_main(const int* __restrict__ tpe, const float* __restrict__ w_base,
          const float* __restrict__ w_b, float* __restrict__ out)
{
    extern __shared__ __align__(16) float sm[];
    const uint32_t sbase = smem_u32(sm);

    const int tid = threadIdx.x;
    const int m0 = blockIdx.x * BM;     // m fastest: wave shares weight n-slice in L2
    const int n0 = blockIdx.y * BN;
    const int e = find_expert(tpe, m0);
    const float* wbase = w_base + (size_t)e * DIN * DOUT + n0;
    const float* wlora = w_b + (size_t)e * RNK * DOUT + n0;
    const float* xa = xR_g + (size_t)m0 * DIN;
    const float* ga = g_mid + (size_t)m0 * RNK;

    const int warp = tid >> 5, lane = tid & 31;
    const int wm = warp >> 2, wn = warp & 3;
    const int g = lane >> 2, t = lane & 3;

    auto load_stage = [&](int kt, int s) {
        const int k0 = kt * BK;
        const bool lora = (k0 >= DIN);
        const uint32_t abase = sbase + (uint32_t)(s * STAGE_FL) * 4u;
        const uint32_t bbase = abase + A_FL * 4u;
#pragma unroll
        for (int i = 0; i < 4; ++i) {
            int idx = tid + i * 256;
            int row = idx >> 3, q = (idx & 7) * 4;
            const float* src = lora ? ga + (size_t)row * RNK + (k0 - DIN) + q
                                    : xa + (size_t)row * DIN + k0 + q;
            cp16(abase + (uint32_t)(row * AST + q) * 4u, src);
        }
#pragma unroll
        for (int i = 0; i < 4; ++i) {
            int idx = tid + i * 256;
            int row = idx >> 5, c = (idx & 31) * 4;
            const float* src = lora ? wlora + (size_t)(k0 - DIN + row) * DOUT + c
                                    : wbase + (size_t)(k0 + row) * DOUT + c;
            cp16(bbase + (uint32_t)(row * BST + c) * 4u, src);
        }
    };

    float acc[4][4][4];
#pragma unroll
    for (int i = 0; i < 4; i++)
#pragma unroll
        for (int j = 0; j < 4; j++)
#pragma unroll
            for (int k = 0; k < 4; k++) acc[i][j][k] = 0.f;

    // prologue: prefetch STG-1 stages
#pragma unroll
    for (int p = 0; p < STG - 1; ++p) { load_stage(p, p); CP_COMMIT(); }

#pragma unroll 1
    for (int kt = 0; kt < NKT; ++kt) {
        CP_WAIT(STG - 2);
        __syncthreads();
        const int kp = kt + STG - 1;
        if (kp < NKT) load_stage(kp, kp % STG);
        CP_COMMIT();

        unsigned* Ab = (unsigned*)sm + (kt % STG) * STAGE_FL;
        unsigned* Bb = Ab + A_FL;
#pragma unroll
        for (int ks = 0; ks < 4; ++ks) {
            const int kk = ks * 8;
            unsigned af[4][4], bf[4][2];
#pragma unroll
            for (int mt = 0; mt < 4; ++mt) {
                int r = wm * 64 + mt * 16;
                af[mt][0] = Ab[(r + g) * AST + kk + t];
                af[mt][1] = Ab[(r + g + 8) * AST + kk + t];
                af[mt][2] = Ab[(r + g) * AST + kk + t + 4];
                af[mt][3] = Ab[(r + g + 8) * AST + kk + t + 4];
            }
#pragma unroll
            for (int nt = 0; nt < 4; ++nt) {
                int c = wn * 32 + nt * 8 + g;
                bf[nt][0] = Bb[(kk + t) * BST + c];
                bf[nt][1] = Bb[(kk + t + 4) * BST + c];
            }
#pragma unroll
            for (int mt = 0; mt < 4; ++mt)
#pragma unroll
                for (int nt = 0; nt < 4; ++nt)
                    mma8(acc[mt][nt], af[mt][0], af[mt][1], af[mt][2], af[mt][3],
                         bf[nt][0], bf[nt][1]);
        }
    }

#pragma unroll
    for (int mt = 0; mt < 4; ++mt)
#pragma unroll
        for (int nt = 0; nt < 4; ++nt) {
            int r = m0 + wm * 64 + mt * 16 + g;
            int c = n0 + wn * 32 + nt * 8 + 2 * t;
            float2 v0 = {acc[mt][nt][0], acc[mt][nt][1]};
            float2 v1 = {acc[mt][nt][2], acc[mt][nt][3]};
            *(float2*)&out[(size_t)r * DOUT + c] = v0;
            *(float2*)&out[(size_t)(r + 8) * DOUT + c] = v1;
        }
}

// ---------------------------------------------------------------------------
extern "C" void kernel_launch(void* const* d_in, const int* in_sizes, int n_in,
                              void* d_out, int out_size) {
    const float* x      = (const float*)d_in[0];
    const int*   tpe    = (const int*)d_in[1];
    const float* w_base = (const float*)d_in[2];
    const float* w_a    = (const float*)d_in[3];
    const float* w_b    = (const float*)d_in[4];
    float* out = (float*)d_out;
    (void)in_sizes; (void)n_in; (void)out_size;

    // 0) pre-round x -> xR (tf32 rna)
    round_x_kernel<<<(TOK * DIN) / 1024, 256>>>(x);

    // 1) LoRA mid
    const int smem1 = 2 * (128 * 36 + 32 * 72) * 4;
    cudaFuncSetAttribute(lora_mid_kernel, cudaFuncAttributeMaxDynamicSharedMemorySize, smem1);
    lora_mid_kernel<<<dim3(1, TOK / 128), 256, smem1>>>(x, tpe, w_a);

    // 2) main GEMM (composite K = 2112)
    cudaFuncSetAttribute(gemm_main, cudaFuncAttributeMaxDynamicSharedMemorySize, GEMM_SMEM);
    gemm_main<<<dim3(TOK / BM, DOUT / BN), 256, GEMM_SMEM>>>(tpe, w_base, w_b, out);
}

// round 4
// speedup vs baseline: 1.6554x; 1.2348x over previous
#include <cuda_runtime.h>
#include <cuda_fp16.h>
#include <cstdint>

#define NUM_E 8
#define TOK   16384
#define DIN   2048
#define DOUT  2048
#define RNK   64
#define LSCALE 2.0f

// ---------------------------------------------------------------------------
// Scratch (allocation-free device globals)
// ---------------------------------------------------------------------------
__device__ __half xh_g[(size_t)TOK * DIN];                 // rna fp16 x
__device__ __half wT_g[(size_t)NUM_E * DOUT * DIN];        // w_base^T fp16 [E][N][K]
__device__ __half wbT_g[(size_t)NUM_E * DOUT * RNK];       // w_b^T fp16 [E][N][R]
__device__ __half gmid_g[(size_t)TOK * RNK];               // fp16 SCALE*(x@w_a)

// fp32 -> tf32 rna (for the small lora_mid GEMM)
__device__ __forceinline__ unsigned f2tf(float f) {
    unsigned u;
    asm("cvt.rna.tf32.f32 %0, %1;" : "=r"(u) : "f"(f));
    return u;
}

__device__ __forceinline__ int find_expert(const int* __restrict__ tpe, int m0) {
    int e = 0, cum = 0;
#pragma unroll
    for (int i = 0; i < NUM_E; ++i) {
        cum += tpe[i];
        if (m0 >= cum) e++;
    }
    return e;
}

__device__ __forceinline__ uint32_t smem_u32(const void* p) {
    uint32_t a;
    asm("{ .reg .u64 t; cvta.to.shared.u64 t, %1; cvt.u32.u64 %0, t; }"
        : "=r"(a) : "l"(p));
    return a;
}

__device__ __forceinline__ void cp16(uint32_t dst, const void* src) {
    asm volatile("cp.async.cg.shared.global [%0], [%1], 16;" :: "r"(dst), "l"(src));
}
#define CP_COMMIT() asm volatile("cp.async.commit_group;" ::: "memory")
#define CP_WAIT(n)  asm volatile("cp.async.wait_group %0;" :: "n"(n) : "memory")

// fp16 MMA: D[16x8] f32 += A[16x16] f16 * B[16x8] f16
__device__ __forceinline__ void mma16(float* c,
                                      unsigned a0, unsigned a1, unsigned a2, unsigned a3,
                                      unsigned b0, unsigned b1) {
    asm volatile(
        "mma.sync.aligned.m16n8k16.row.col.f32.f16.f16.f32 "
        "{%0,%1,%2,%3}, {%4,%5,%6,%7}, {%8,%9}, {%0,%1,%2,%3};"
        : "+f"(c[0]), "+f"(c[1]), "+f"(c[2]), "+f"(c[3])
        : "r"(a0), "r"(a1), "r"(a2), "r"(a3), "r"(b0), "r"(b1));
}

// tf32 MMA (lora_mid only)
__device__ __forceinline__ void mma8(float* c,
                                     unsigned a0, unsigned a1, unsigned a2, unsigned a3,
                                     unsigned b0, unsigned b1) {
    asm volatile(
        "mma.sync.aligned.m16n8k8.row.col.f32.tf32.tf32.f32 "
        "{%0,%1,%2,%3}, {%4,%5,%6,%7}, {%8,%9}, {%0,%1,%2,%3};"
        : "+f"(c[0]), "+f"(c[1]), "+f"(c[2]), "+f"(c[3])
        : "r"(a0), "r"(a1), "r"(a2), "r"(a3), "r"(b0), "r"(b1));
}

// ---------------------------------------------------------------------------
// Conversion kernels
// ---------------------------------------------------------------------------
__global__ void __launch_bounds__(256)
conv_x_kernel(const float* __restrict__ x) {
    size_t i = ((size_t)blockIdx.x * 256 + threadIdx.x) * 8;
    float4 v0 = *(const float4*)(x + i);
    float4 v1 = *(const float4*)(x + i + 4);
    __half2 h[4];
    h[0] = __floats2half2_rn(v0.x, v0.y);
    h[1] = __floats2half2_rn(v0.z, v0.w);
    h[2] = __floats2half2_rn(v1.x, v1.y);
    h[3] = __floats2half2_rn(v1.z, v1.w);
    *(uint4*)(xh_g + i) = *(uint4*)h;
}

// transpose + fp16-round: src [E][K][N] f32 -> dst [E][N][K] f16
__global__ void __launch_bounds__(1024)
conv_wT_kernel(const float* __restrict__ src, __half* __restrict__ dst,
               int K, int N) {
    __shared__ float tile[32][33];
    const int e = blockIdx.z;
    const float* s = src + (size_t)e * K * N;
    __half* d = dst + (size_t)e * K * N;
    const int k0 = blockIdx.y * 32, n0 = blockIdx.x * 32;
    const int tx = threadIdx.x, ty = threadIdx.y;
    tile[ty][tx] = s[(size_t)(k0 + ty) * N + n0 + tx];
    __syncthreads();
    d[(size_t)(n0 + ty) * K + k0 + tx] = __float2half_rn(tile[tx][ty]);
}

// ---------------------------------------------------------------------------
// Kernel 1: gmid = fp16_rna(LSCALE * (x @ w_a[e]))   (tf32 mma)
// ---------------------------------------------------------------------------
__global__ void __launch_bounds__(256)
lora_mid_kernel(const float* __restrict__ x, const int* __restrict__ tpe,
                const float* __restrict__ w_a)
{
    const int BMm = 128, BKm = 32;
    const int AST1 = 36;
    const int BST1 = 72;
    extern __shared__ __align__(16) unsigned smem1[];
    unsigned* As = smem1;
    unsigned* Bs = smem1 + 2 * BMm * AST1;

    const int tid = threadIdx.x;
    const int m0 = blockIdx.y * BMm;
    const int e = find_expert(tpe, m0);
    const float* wa = w_a + (size_t)e * DIN * RNK;

    const int warp = tid >> 5, lane = tid & 31;
    const int wm = warp >> 1, wn = warp & 1;
    const int g = lane >> 2, t = lane & 3;

    float acc[2][4][4];
#pragma unroll
    for (int i = 0; i < 2; i++)
#pragma unroll
        for (int j = 0; j < 4; j++)
#pragma unroll
            for (int k = 0; k < 4; k++) acc[i][j][k] = 0.f;

    float4 ra[4], rb[2];
    auto ldg = [&](int kt) {
        const int k0 = kt * BKm;
#pragma unroll
        for (int i = 0; i < 4; ++i) {
            int idx = tid + i * 256;
            int row = idx >> 3, c4 = (idx & 7) * 4;
            ra[i] = *(const float4*)&x[(size_t)(m0 + row) * DIN + k0 + c4];
        }
#pragma unroll
        for (int i = 0; i < 2; ++i) {
            int idx = tid + i * 256;
            int row = idx >> 4, c4 = (idx & 15) * 4;
            rb[i] = *(const float4*)&wa[(size_t)(k0 + row) * RNK + c4];
        }
    };
    auto sts = [&](int buf) {
        unsigned* Ab = As + buf * BMm * AST1;
        unsigned* Bb = Bs + buf * BKm * BST1;
#pragma unroll
        for (int i = 0; i < 4; ++i) {
            int idx = tid + i * 256;
            int row = idx >> 3, c4 = (idx & 7) * 4;
            uint4 s = make_uint4(f2tf(ra[i].x), f2tf(ra[i].y), f2tf(ra[i].z), f2tf(ra[i].w));
            *(uint4*)&Ab[row * AST1 + c4] = s;
        }
#pragma unroll
        for (int i = 0; i < 2; ++i) {
            int idx = tid + i * 256;
            int row = idx >> 4, c4 = (idx & 15) * 4;
            uint4 s = make_uint4(f2tf(rb[i].x), f2tf(rb[i].y), f2tf(rb[i].z), f2tf(rb[i].w));
            *(uint4*)&Bb[row * BST1 + c4] = s;
        }
    };

    const int NKTm = DIN / BKm;
    ldg(0); sts(0); __syncthreads();

    for (int kt = 0; kt < NKTm; ++kt) {
        const int buf = kt & 1;
        if (kt + 1 < NKTm) ldg(kt + 1);
        unsigned* Ab = As + buf * BMm * AST1;
        unsigned* Bb = Bs + buf * BKm * BST1;
#pragma unroll
        for (int ks = 0; ks < 4; ++ks) {
            const int kk = ks * 8;
            unsigned af[2][4], bf[4][2];
#pragma unroll
            for (int mt = 0; mt < 2; ++mt) {
                int r = wm * 32 + mt * 16;
                af[mt][0] = Ab[(r + g) * AST1 + kk + t];
                af[mt][1] = Ab[(r + g + 8) * AST1 + kk + t];
                af[mt][2] = Ab[(r + g) * AST1 + kk + t + 4];
                af[mt][3] = Ab[(r + g + 8) * AST1 + kk + t + 4];
            }
#pragma unroll
            for (int nt = 0; nt < 4; ++nt) {
                int c = wn * 32 + nt * 8 + g;
                bf[nt][0] = Bb[(kk + t) * BST1 + c];
                bf[nt][1] = Bb[(kk + t + 4) * BST1 + c];
            }
#pragma unroll
            for (int mt = 0; mt < 2; ++mt)
#pragma unroll
                for (int nt = 0; nt < 4; ++nt)
                    mma8(acc[mt][nt], af[mt][0], af[mt][1], af[mt][2], af[mt][3],
                         bf[nt][0], bf[nt][1]);
        }
        if (kt + 1 < NKTm) sts((kt + 1) & 1);
        __syncthreads();
    }

#pragma unroll
    for (int mt = 0; mt < 2; ++mt)
#pragma unroll
        for (int nt = 0; nt < 4; ++nt) {
            int r = m0 + wm * 32 + mt * 16 + g;
            int c = wn * 32 + nt * 8 + 2 * t;
            __half2 v0 = __floats2half2_rn(LSCALE * acc[mt][nt][0], LSCALE * acc[mt][nt][1]);
            __half2 v1 = __floats2half2_rn(LSCALE * acc[mt][nt][2], LSCALE * acc[mt][nt][3]);
            *(__half2*)&gmid_g[(size_t)r * RNK + c] = v0;
            *(__half2*)&gmid_g[(size_t)(r + 8) * RNK + c] = v1;
        }
}

// ---------------------------------------------------------------------------
// Kernel 2: main GEMM (fp16 m16n8k16). out = xh @ wT[e]^T + gmid @ wbT[e]^T
// Composite K = 2112. BM=128 BN=128 BK=32, 4-stage cp.async, 8 warps, 2 CTA/SM.
// A smem [m][k] stride 40 halves; B smem [n][k] stride 40 halves (both
// conflict-free: bank = (20g+t)%32 hits all 32 banks per warp).
// ---------------------------------------------------------------------------
#define BM   128
#define BN   128
#define BK   32
#define STG  4
#define AST  40
#define BST  40
#define A_H  (BM * AST)                 // 5120 halves
#define B_H  (BN * BST)                 // 5120 halves
#define STAGE_H (A_H + B_H)             // 10240 halves = 20480 B
#define NKT  ((DIN + RNK) / BK)         // 66
#define GEMM_SMEM (STG * STAGE_H * 2)   // 81920 B

__global__ void __launch_bounds__(256, 2)
gemm_main(const int* __restrict__ tpe, float* __restrict__ out)
{
    extern __shared__ __align__(16) __half sm[];
    const uint32_t sbase = smem_u32(sm);

    const int tid = threadIdx.x;
    const int m0 = blockIdx.x * BM;   // m fastest: wave shares weight n-slice via L2
    const int n0 = blockIdx.y * BN;
    const int e = find_expert(tpe, m0);
    const __half* wT  = wT_g  + (size_t)e * DOUT * DIN + (size_t)n0 * DIN;
    const __half* wbT = wbT_g + (size_t)e * DOUT * RNK + (size_t)n0 * RNK;
    const __half* xa = xh_g + (size_t)m0 * DIN;
    const __half* ga = gmid_g + (size_t)m0 * RNK;

    const int warp = tid >> 5, lane = tid & 31;
    const int wm = warp >> 2, wn = warp & 3;
    const int g = lane >> 2, t = lane & 3;

    auto load_stage = [&](int kt, int s) {
        const int k0 = kt * BK;
        const bool lora = (k0 >= DIN);
        const uint32_t abase = sbase + (uint32_t)(s * STAGE_H) * 2u;
        const uint32_t bbase = abase + A_H * 2u;
#pragma unroll
        for (int i = 0; i < 2; ++i) {
            int idx = tid + i * 256;
            int row = idx >> 2, q = (idx & 3) * 8;   // 8 halves = 16B
            const __half* src = lora ? ga + (size_t)row * RNK + (k0 - DIN) + q
                                     : xa + (size_t)row * DIN + k0 + q;
            cp16(abase + (uint32_t)(row * AST + q) * 2u, src);
        }
#pragma unroll
        for (int i = 0; i < 2; ++i) {
            int idx = tid + i * 256;
            int n = idx >> 2, q = (idx & 3) * 8;
            const __half* src = lora ? wbT + (size_t)n * RNK + (k0 - DIN) + q
                                     : wT + (size_t)n * DIN + k0 + q;
            cp16(bbase + (uint32_t)(n * BST + q) * 2u, src);
        }
    };

    float acc[4][4][4];
#pragma unroll
    for (int i = 0; i < 4; i++)
#pragma unroll
        for (int j = 0; j < 4; j++)
#pragma unroll
            for (int k = 0; k < 4; k++) acc[i][j][k] = 0.f;

#pragma unroll
    for (int p = 0; p < STG - 1; ++p) { load_stage(p, p); CP_COMMIT(); }

#pragma unroll 1
    for (int kt = 0; kt < NKT; ++kt) {
        CP_WAIT(STG - 2);
        __syncthreads();
        const int kp = kt + STG - 1;
        if (kp < NKT) load_stage(kp, kp % STG);
        CP_COMMIT();

        const __half* Ab = sm + (kt % STG) * STAGE_H;
        const __half* Bb = Ab + A_H;
#pragma unroll
        for (int ks = 0; ks < 2; ++ks) {
            const int kk = ks * 16;
            unsigned af[4][4], bf[4][2];
#pragma unroll
            for (int mt = 0; mt < 4; ++mt) {
                int r = wm * 64 + mt * 16;
                af[mt][0] = *(const unsigned*)(Ab + (r + g) * AST + kk + 2 * t);
                af[mt][1] = *(const unsigned*)(Ab + (r + g + 8) * AST + kk + 2 * t);
                af[mt][2] = *(const unsigned*)(Ab + (r + g) * AST + kk + 2 * t + 8);
                af[mt][3] = *(const unsigned*)(Ab + (r + g + 8) * AST + kk + 2 * t + 8);
            }
#pragma unroll
            for (int nt = 0; nt < 4; ++nt) {
                int c = wn * 32 + nt * 8 + g;
                bf[nt][0] = *(const unsigned*)(Bb + c * BST + kk + 2 * t);
                bf[nt][1] = *(const unsigned*)(Bb + c * BST + kk + 2 * t + 8);
            }
#pragma unroll
            for (int mt = 0; mt < 4; ++mt)
#pragma unroll
                for (int nt = 0; nt < 4; ++nt)
                    mma16(acc[mt][nt], af[mt][0], af[mt][1], af[mt][2], af[mt][3],
                          bf[nt][0], bf[nt][1]);
        }
    }

#pragma unroll
    for (int mt = 0; mt < 4; ++mt)
#pragma unroll
        for (int nt = 0; nt < 4; ++nt) {
            int r = m0 + wm * 64 + mt * 16 + g;
            int c = n0 + wn * 32 + nt * 8 + 2 * t;
            float2 v0 = {acc[mt][nt][0], acc[mt][nt][1]};
            float2 v1 = {acc[mt][nt][2], acc[mt][nt][3]};
            *(float2*)&out[(size_t)r * DOUT + c] = v0;
            *(float2*)&out[(size_t)(r + 8) * DOUT + c] = v1;
        }
}

// ---------------------------------------------------------------------------
extern "C" void kernel_launch(void* const* d_in, const int* in_sizes, int n_in,
                              void* d_out, int out_size) {
    const float* x      = (const float*)d_in[0];
    const int*   tpe    = (const int*)d_in[1];
    const float* w_base = (const float*)d_in[2];
    const float* w_a    = (const float*)d_in[3];
    const float* w_b    = (const float*)d_in[4];
    float* out = (float*)d_out;
    (void)in_sizes; (void)n_in; (void)out_size;

    __half* wT = nullptr;  cudaGetSymbolAddress((void**)&wT,  wT_g);
    __half* wbT = nullptr; cudaGetSymbolAddress((void**)&wbT, wbT_g);

    // 0) conversions (rna fp16)
    conv_x_kernel<<<(TOK * DIN) / 2048, 256>>>(x);
    conv_wT_kernel<<<dim3(DOUT / 32, DIN / 32, NUM_E), dim3(32, 32)>>>(w_base, wT, DIN, DOUT);
    conv_wT_kernel<<<dim3(DOUT / 32, RNK / 32, NUM_E), dim3(32, 32)>>>(w_b, wbT, RNK, DOUT);

    // 1) LoRA mid
    const int smem1 = 2 * (128 * 36 + 32 * 72) * 4;
    cudaFuncSetAttribute(lora_mid_kernel, cudaFuncAttributeMaxDynamicSharedMemorySize, smem1);
    lora_mid_kernel<<<dim3(1, TOK / 128), 256, smem1>>>(x, tpe, w_a);

    // 2) main GEMM (composite K = 2112)
    cudaFuncSetAttribute(gemm_main, cudaFuncAttributeMaxDynamicSharedMemorySize, GEMM_SMEM);
    gemm_main<<<dim3(TOK / BM, DOUT / BN), 256, GEMM_SMEM>>>(tpe, out);
}

// round 6
// speedup vs baseline: 2.9652x; 1.7913x over previous
#include <cuda_runtime.h>
#include <cuda_fp16.h>
#include <cstdint>

#define NUM_E 8
#define TOK   16384
#define DIN   2048
#define DOUT  2048
#define RNK   64
#define LSCALE 2.0f

// ---------------------------------------------------------------------------
// Scratch (allocation-free device globals) — all fp16, rna-rounded
// ---------------------------------------------------------------------------
__device__ __half xh_g[(size_t)TOK * DIN];                // x
__device__ __half wh_g[(size_t)NUM_E * DIN * DOUT];       // w_base [E][K][N]
__device__ __half wah_g[(size_t)NUM_E * DIN * RNK];       // w_a    [E][K][R]
__device__ __half wbh_g[(size_t)NUM_E * RNK * DOUT];      // w_b    [E][R][N]
__device__ __half gmid_g[(size_t)TOK * RNK];              // SCALE*(x@w_a)

__device__ __forceinline__ int find_expert(const int* __restrict__ tpe, int m0) {
    int e = 0, cum = 0;
#pragma unroll
    for (int i = 0; i < NUM_E; ++i) {
        cum += tpe[i];
        if (m0 >= cum) e++;
    }
    return e;
}

__device__ __forceinline__ uint32_t smem_u32(const void* p) {
    uint32_t a;
    asm("{ .reg .u64 t; cvta.to.shared.u64 t, %1; cvt.u32.u64 %0, t; }"
        : "=r"(a) : "l"(p));
    return a;
}

__device__ __forceinline__ void cp16(uint32_t dst, const void* src) {
    asm volatile("cp.async.cg.shared.global [%0], [%1], 16;" :: "r"(dst), "l"(src));
}
#define CP_COMMIT() asm volatile("cp.async.commit_group;" ::: "memory")
#define CP_WAIT(n)  asm volatile("cp.async.wait_group %0;" :: "n"(n) : "memory")

__device__ __forceinline__ void ldsm4(unsigned& r0, unsigned& r1, unsigned& r2,
                                      unsigned& r3, uint32_t addr) {
    asm volatile("ldmatrix.sync.aligned.m8n8.x4.shared.b16 {%0,%1,%2,%3}, [%4];"
                 : "=r"(r0), "=r"(r1), "=r"(r2), "=r"(r3) : "r"(addr));
}
__device__ __forceinline__ void ldsm4t(unsigned& r0, unsigned& r1, unsigned& r2,
                                       unsigned& r3, uint32_t addr) {
    asm volatile("ldmatrix.sync.aligned.m8n8.x4.trans.shared.b16 {%0,%1,%2,%3}, [%4];"
                 : "=r"(r0), "=r"(r1), "=r"(r2), "=r"(r3) : "r"(addr));
}

__device__ __forceinline__ void mma16(float* c,
                                      unsigned a0, unsigned a1, unsigned a2, unsigned a3,
                                      unsigned b0, unsigned b1) {
    asm volatile(
        "mma.sync.aligned.m16n8k16.row.col.f32.f16.f16.f32 "
        "{%0,%1,%2,%3}, {%4,%5,%6,%7}, {%8,%9}, {%0,%1,%2,%3};"
        : "+f"(c[0]), "+f"(c[1]), "+f"(c[2]), "+f"(c[3])
        : "r"(a0), "r"(a1), "r"(a2), "r"(a3), "r"(b0), "r"(b1));
}

// ---------------------------------------------------------------------------
// Kernel 0: straight fp32 -> fp16 (rna) conversion, 8 elems/thread
// ---------------------------------------------------------------------------
__global__ void __launch_bounds__(256)
conv_half_kernel(const float* __restrict__ src, __half* __restrict__ dst) {
    size_t i = ((size_t)blockIdx.x * 256 + threadIdx.x) * 8;
    float4 v0 = *(const float4*)(src + i);
    float4 v1 = *(const float4*)(src + i + 4);
    __half2 h[4];
    h[0] = __floats2half2_rn(v0.x, v0.y);
    h[1] = __floats2half2_rn(v0.z, v0.w);
    h[2] = __floats2half2_rn(v1.x, v1.y);
    h[3] = __floats2half2_rn(v1.z, v1.w);
    *(uint4*)(dst + i) = *(uint4*)h;
}

// ---------------------------------------------------------------------------
// Kernel 1: gmid = fp16(LSCALE * (xh @ wah[e]))   fp16 mma + ldmatrix
// BM=128, BN=64, BK=32; 4 warps (2m x 2n), warp tile 64x32; 4-stage cp.async.
// ---------------------------------------------------------------------------
#define M_AST 40
#define M_BST 72
#define M_AH  (128 * M_AST)
#define M_BH  (32 * M_BST)
#define M_STAGE (M_AH + M_BH)
#define M_SMEM  (4 * M_STAGE * 2)

__global__ void __launch_bounds__(128, 2)
lora_mid_kernel(const int* __restrict__ tpe)
{
    extern __shared__ __align__(16) __half sm[];
    const uint32_t sbase = smem_u32(sm);

    const int tid = threadIdx.x;
    const int m0 = blockIdx.x * 128;
    const int e = find_expert(tpe, m0);
    const __half* xa = xh_g + (size_t)m0 * DIN;
    const __half* wa = wah_g + (size_t)e * DIN * RNK;

    const int warp = tid >> 5, lane = tid & 31;
    const int wm = warp >> 1, wn = warp & 1;
    const int g = lane >> 2, t = lane & 3;

    // ldmatrix per-thread offsets
    const int arow = ((lane >> 3) & 1) * 8 + (lane & 7);
    const int akoff = (lane >> 4) * 8;
    const int bm = lane >> 3;
    const int bkrow = (bm & 1) * 8 + (lane & 7);
    const int bnoff = (bm >> 1) * 8;

    auto load_stage = [&](int kt, int s) {
        const int k0 = kt * 32;
        const uint32_t abase = sbase + (uint32_t)(s * M_STAGE) * 2u;
        const uint32_t bbase = abase + M_AH * 2u;
#pragma unroll
        for (int i = 0; i < 4; ++i) {
            int idx = tid + i * 128;
            int row = idx >> 2, q = (idx & 3) * 8;
            cp16(abase + (uint32_t)(row * M_AST + q) * 2u,
                 xa + (size_t)row * DIN + k0 + q);
        }
#pragma unroll
        for (int i = 0; i < 2; ++i) {
            int idx = tid + i * 128;
            int row = idx >> 3, q = (idx & 7) * 8;
            cp16(bbase + (uint32_t)(row * M_BST + q) * 2u,
                 wa + (size_t)(k0 + row) * RNK + q);
        }
    };

    float acc[4][4][4];
#pragma unroll
    for (int i = 0; i < 4; i++)
#pragma unroll
        for (int j = 0; j < 4; j++)
#pragma unroll
            for (int k = 0; k < 4; k++) acc[i][j][k] = 0.f;

#pragma unroll
    for (int p = 0; p < 3; ++p) { load_stage(p, p); CP_COMMIT(); }

    const int NKTm = DIN / 32;   // 64
#pragma unroll 1
    for (int kt = 0; kt < NKTm; ++kt) {
        CP_WAIT(2);
        __syncthreads();
        const int kp = kt + 3;
        if (kp < NKTm) load_stage(kp, kp & 3);
        CP_COMMIT();

        const uint32_t Ab = sbase + (uint32_t)((kt & 3) * M_STAGE) * 2u;
        const uint32_t Bb = Ab + M_AH * 2u;
        const uint32_t aoff = Ab + (uint32_t)((wm * 64 + arow) * M_AST + akoff) * 2u;
        const uint32_t boff = Bb + (uint32_t)(bkrow * M_BST + wn * 32 + bnoff) * 2u;
#pragma unroll
        for (int ks = 0; ks < 2; ++ks) {
            const int kk = ks * 16;
            unsigned af[4][4], bf[4][2];
#pragma unroll
            for (int mt = 0; mt < 4; ++mt)
                ldsm4(af[mt][0], af[mt][1], af[mt][2], af[mt][3],
                      aoff + (uint32_t)(mt * 16 * M_AST + kk) * 2u);
#pragma unroll
            for (int p = 0; p < 2; ++p)
                ldsm4t(bf[2 * p][0], bf[2 * p][1], bf[2 * p + 1][0], bf[2 * p + 1][1],
                       boff + (uint32_t)(kk * M_BST + p * 16) * 2u);
#pragma unroll
            for (int mt = 0; mt < 4; ++mt)
#pragma unroll
                for (int nt = 0; nt < 4; ++nt)
                    mma16(acc[mt][nt], af[mt][0], af[mt][1], af[mt][2], af[mt][3],
                          bf[nt][0], bf[nt][1]);
        }
    }

#pragma unroll
    for (int mt = 0; mt < 4; ++mt)
#pragma unroll
        for (int nt = 0; nt < 4; ++nt) {
            int r = m0 + wm * 64 + mt * 16 + g;
            int c = wn * 32 + nt * 8 + 2 * t;
            __half2 v0 = __floats2half2_rn(LSCALE * acc[mt][nt][0], LSCALE * acc[mt][nt][1]);
            __half2 v1 = __floats2half2_rn(LSCALE * acc[mt][nt][2], LSCALE * acc[mt][nt][3]);
            *(__half2*)&gmid_g[(size_t)r * RNK + c] = v0;
            *(__half2*)&gmid_g[(size_t)(r + 8) * RNK + c] = v1;
        }
}

// ---------------------------------------------------------------------------
// Kernel 2: main GEMM. out = xh @ wh[e] + gmid @ wbh[e]  (composite K = 2112)
// BM=128 BN=128 BK=32; 4 warps (2x2), warp tile 64x64; ldmatrix + trans;
// 4-stage cp.async; 2 CTAs/SM.
// ---------------------------------------------------------------------------
#define AST 40
#define BST 136
#define A_H (128 * AST)                 // 5120 halves
#define B_H (32 * BST)                  // 4352 halves
#define STAGE_H (A_H + B_H)             // 9472 halves
#define NKT ((DIN + RNK) / 32)          // 66
#define GEMM_SMEM (4 * STAGE_H * 2)     // 75776 B

__global__ void __launch_bounds__(128, 2)
gemm_main(const int* __restrict__ tpe, float* __restrict__ out)
{
    extern __shared__ __align__(16) __half sm[];
    const uint32_t sbase = smem_u32(sm);

    const int tid = threadIdx.x;
    const int m0 = blockIdx.x * 128;   // m fastest: wave shares weight slice via L2
    const int n0 = blockIdx.y * 128;
    const int e = find_expert(tpe, m0);
    const __half* wb  = wh_g  + (size_t)e * DIN * DOUT + n0;
    const __half* wlb = wbh_g + (size_t)e * RNK * DOUT + n0;
    const __half* xa = xh_g + (size_t)m0 * DIN;
    const __half* ga = gmid_g + (size_t)m0 * RNK;

    const int warp = tid >> 5, lane = tid & 31;
    const int wm = warp >> 1, wn = warp & 1;
    const int g = lane >> 2, t = lane & 3;

    const int arow = ((lane >> 3) & 1) * 8 + (lane & 7);
    const int akoff = (lane >> 4) * 8;
    const int bm = lane >> 3;
    const int bkrow = (bm & 1) * 8 + (lane & 7);
    const int bnoff = (bm >> 1) * 8;

    auto load_stage = [&](int kt, int s) {
        const int k0 = kt * 32;
        const bool lora = (k0 >= DIN);
        const uint32_t abase = sbase + (uint32_t)(s * STAGE_H) * 2u;
        const uint32_t bbase = abase + A_H * 2u;
#pragma unroll
        for (int i = 0; i < 4; ++i) {
            int idx = tid + i * 128;
            int row = idx >> 2, q = (idx & 3) * 8;
            const __half* src = lora ? ga + (size_t)row * RNK + (k0 - DIN) + q
                                     : xa + (size_t)row * DIN + k0 + q;
            cp16(abase + (uint32_t)(row * AST + q) * 2u, src);
        }
        // B tile: 32 k-rows x 128 n = 4096 halves = 512 cp16 -> 4 iterations
#pragma unroll
        for (int i = 0; i < 4; ++i) {
            int idx = tid + i * 128;
            int row = idx >> 4, q = (idx & 15) * 8;
            const __half* src = lora ? wlb + (size_t)(k0 - DIN + row) * DOUT + q
                                     : wb + (size_t)(k0 + row) * DOUT + q;
            cp16(bbase + (uint32_t)(row * BST + q) * 2u, src);
        }
    };

    float acc[4][8][4];
#pragma unroll
    for (int i = 0; i < 4; i++)
#pragma unroll
        for (int j = 0; j < 8; j++)
#pragma unroll
            for (int k = 0; k < 4; k++) acc[i][j][k] = 0.f;

#pragma unroll
    for (int p = 0; p < 3; ++p) { load_stage(p, p); CP_COMMIT(); }

#pragma unroll 1
    for (int kt = 0; kt < NKT; ++kt) {
        CP_WAIT(2);
        __syncthreads();
        const int kp = kt + 3;
        if (kp < NKT) load_stage(kp, kp & 3);
        CP_COMMIT();

        const uint32_t Ab = sbase + (uint32_t)((kt & 3) * STAGE_H) * 2u;
        const uint32_t Bb = Ab + A_H * 2u;
        const uint32_t aoff = Ab + (uint32_t)((wm * 64 + arow) * AST + akoff) * 2u;
        const uint32_t boff = Bb + (uint32_t)(bkrow * BST + wn * 64 + bnoff) * 2u;
#pragma unroll
        for (int ks = 0; ks < 2; ++ks) {
            const int kk = ks * 16;
            unsigned af[4][4], bf[8][2];
#pragma unroll
            for (int mt = 0; mt < 4; ++mt)
                ldsm4(af[mt][0], af[mt][1], af[mt][2], af[mt][3],
                      aoff + (uint32_t)(mt * 16 * AST + kk) * 2u);
#pragma unroll
            for (int p = 0; p < 4; ++p)
                ldsm4t(bf[2 * p][0], bf[2 * p][1], bf[2 * p + 1][0], bf[2 * p + 1][1],
                       boff + (uint32_t)(kk * BST + p * 16) * 2u);
#pragma unroll
            for (int mt = 0; mt < 4; ++mt)
#pragma unroll
                for (int nt = 0; nt < 8; ++nt)
                    mma16(acc[mt][nt], af[mt][0], af[mt][1], af[mt][2], af[mt][3],
                          bf[nt][0], bf[nt][1]);
        }
    }

#pragma unroll
    for (int mt = 0; mt < 4; ++mt)
#pragma unroll
        for (int nt = 0; nt < 8; ++nt) {
            int r = m0 + wm * 64 + mt * 16 + g;
            int c = n0 + wn * 64 + nt * 8 + 2 * t;
            float2 v0 = {acc[mt][nt][0], acc[mt][nt][1]};
            float2 v1 = {acc[mt][nt][2], acc[mt][nt][3]};
            *(float2*)&out[(size_t)r * DOUT + c] = v0;
            *(float2*)&out[(size_t)(r + 8) * DOUT + c] = v1;
        }
}

// ---------------------------------------------------------------------------
extern "C" void kernel_launch(void* const* d_in, const int* in_sizes, int n_in,
                              void* d_out, int out_size) {
    const float* x      = (const float*)d_in[0];
    const int*   tpe    = (const int*)d_in[1];
    const float* w_base = (const float*)d_in[2];
    const float* w_a    = (const float*)d_in[3];
    const float* w_b    = (const float*)d_in[4];
    float* out = (float*)d_out;
    (void)in_sizes; (void)n_in; (void)out_size;

    __half* xh = nullptr;  cudaGetSymbolAddress((void**)&xh,  xh_g);
    __half* wh = nullptr;  cudaGetSymbolAddress((void**)&wh,  wh_g);
    __half* wah = nullptr; cudaGetSymbolAddress((void**)&wah, wah_g);
    __half* wbh = nullptr; cudaGetSymbolAddress((void**)&wbh, wbh_g);

    // 0) fp32 -> fp16 conversions (no transposes)
    conv_half_kernel<<<(TOK * DIN) / 2048, 256>>>(x, xh);
    conv_half_kernel<<<((size_t)NUM_E * DIN * DOUT) / 2048, 256>>>(w_base, wh);
    conv_half_kernel<<<((size_t)NUM_E * DIN * RNK) / 2048, 256>>>(w_a, wah);
    conv_half_kernel<<<((size_t)NUM_E * RNK * DOUT) / 2048, 256>>>(w_b, wbh);

    // 1) LoRA mid
    cudaFuncSetAttribute(lora_mid_kernel, cudaFuncAttributeMaxDynamicSharedMemorySize, M_SMEM);
    lora_mid_kernel<<<TOK / 128, 128, M_SMEM>>>(tpe);

    // 2) main GEMM (composite K = 2112)
    cudaFuncSetAttribute(gemm_main, cudaFuncAttributeMaxDynamicSharedMemorySize, GEMM_SMEM);
    gemm_main<<<dim3(TOK / 128, DOUT / 128), 128, GEMM_SMEM>>>(tpe, out);
}